// round 12
// baseline (speedup 1.0000x reference)
#include <cuda_runtime.h>
#include <cstdint>
#include <cstddef>

#define B_   4
#define T_   2048
#define DM   1024
#define H_   16
#define DH   64
#define NTOK (B_ * T_)   // 8192

// Scratch (allocation-free rule: __device__ globals)
__device__ float g_qkv[(size_t)NTOK * 3 * DM];   // tf32-rounded qkv
__device__ float g_xa [(size_t)NTOK * DM];       // tf32(x), later tf32(attn out)
__device__ float g_wq [(size_t)DM * 3 * DM];     // tf32(w_qkv)
__device__ float g_wo [(size_t)DM * DM];         // tf32(w_out)

__device__ __forceinline__ void cpa16(float* s, const float* g) {
    uint32_t sa = (uint32_t)__cvta_generic_to_shared(s);
    asm volatile("cp.async.cg.shared.global [%0], [%1], 16;\n" :: "r"(sa), "l"(g));
}
__device__ __forceinline__ void cpa_commit() {
    asm volatile("cp.async.commit_group;\n");
}
__device__ __forceinline__ void cpa_wait0() {
    asm volatile("cp.async.wait_group 0;\n");
}
__device__ __forceinline__ void cpa_wait1() {
    asm volatile("cp.async.wait_group 1;\n");
}
__device__ __forceinline__ uint32_t f2tf32(float x) {
    uint32_t r;
    asm("cvt.rna.tf32.f32 %0, %1;" : "=r"(r) : "f"(x));
    return r;
}
__device__ __forceinline__ uint4 cvt4(float4 v) {
    uint4 u;
    u.x = f2tf32(v.x); u.y = f2tf32(v.y);
    u.z = f2tf32(v.z); u.w = f2tf32(v.w);
    return u;
}
__device__ __forceinline__ float ex2(float x) {
    float r;
    asm("ex2.approx.f32 %0, %1;" : "=f"(r) : "f"(x));
    return r;
}
#define MMA_TF32(CC, AF, B0, B1)                                              \
    asm volatile(                                                             \
        "mma.sync.aligned.m16n8k8.row.col.f32.tf32.tf32.f32 "                 \
        "{%0,%1,%2,%3}, {%4,%5,%6,%7}, {%8,%9}, {%0,%1,%2,%3};"               \
        : "+f"((CC)[0]), "+f"((CC)[1]), "+f"((CC)[2]), "+f"((CC)[3])          \
        : "r"((AF)[0]), "r"((AF)[1]), "r"((AF)[2]), "r"((AF)[3]),             \
          "r"(B0), "r"(B1))

// ---------------------------------------------------------------------------
// Pre-pass: round fp32 -> tf32 bit patterns (pure bandwidth).
// ---------------------------------------------------------------------------
__global__ __launch_bounds__(256) void cvt_tf32(const float4* __restrict__ in,
                                                uint4* __restrict__ out)
{
    const size_t i = (size_t)blockIdx.x * 256 + threadIdx.x;
    out[i] = cvt4(in[i]);
}

// ---------------------------------------------------------------------------
// TF32 tensor-core GEMM, 3-STAGE cp.async pipeline:
// 128x128 CTA tile, k-chunk 32, 256 threads (8 warps, warp tile 32x64),
// buffers mod 3, wait_group 1 in steady state (chunk c+2 streams while c
// computes and c+1 is in flight). Inputs pre-rounded => pure LDS+MMA mainloop.
// ---------------------------------------------------------------------------
#define ASTR 36
#define BSTR 136
#define ASZ  (128 * ASTR)
#define BSZ  (32 * BSTR)
#define GEMM_SMEM (3 * (ASZ + BSZ) * 4)   // 107520 bytes (2 CTAs/SM: 215KB)

template<bool CVTOUT>
__global__ __launch_bounds__(256) void tf32_gemm(const float* __restrict__ A,
                                                 const float* __restrict__ Bm,
                                                 float* __restrict__ C,
                                                 int M, int N, int K)
{
    extern __shared__ float sm[];
    float* As = sm;                  // [3][128][ASTR]
    float* Bs = sm + 3 * ASZ;        // [3][32][BSTR]

    const int tid  = threadIdx.x;
    const int lane = tid & 31;
    const int warp = tid >> 5;
    const int wm   = warp >> 1;
    const int wn   = warp & 1;
    const int lr   = lane >> 2;
    const int lc   = lane & 3;
    const int row0 = blockIdx.y << 7;
    const int col0 = blockIdx.x << 7;

    const int ar = tid >> 3;
    const int ac = (tid & 7) << 2;
    const int br = tid >> 5;
    const int bc = (tid & 31) << 2;

    float acc[2][8][4];
#pragma unroll
    for (int mi = 0; mi < 2; ++mi)
#pragma unroll
        for (int ni = 0; ni < 8; ++ni)
#pragma unroll
            for (int r = 0; r < 4; ++r) acc[mi][ni][r] = 0.f;

    const int nch = K >> 5;
    const float* Ag0 = A + (size_t)(row0 + ar) * K + ac;
    const float* Bg0 = Bm + col0 + bc + (size_t)br * N;

    // prologue: chunks 0 and 1 into buffers 0 and 1 (two commit groups)
#pragma unroll
    for (int p = 0; p < 2; ++p) {
        const int k0 = p << 5;
        float* ab = As + p * ASZ;
        float* bb = Bs + p * BSZ;
#pragma unroll
        for (int it = 0; it < 4; ++it)
            cpa16(ab + (ar + it * 32) * ASTR + ac, Ag0 + k0 + (size_t)(it * 32) * K);
#pragma unroll
        for (int it = 0; it < 4; ++it)
            cpa16(bb + (br + it * 8) * BSTR + bc, Bg0 + (size_t)(k0 + it * 8) * N);
        cpa_commit();
    }

    for (int c = 0; c < nch; ++c) {
        if (c + 1 < nch) cpa_wait1();   // chunk c landed; c+1 may be in flight
        else             cpa_wait0();   // last chunk: nothing else pending
        __syncthreads();                // publish chunk c; buf (c+2)%3 readers done

        if (c + 2 < nch) {              // prefetch chunk c+2
            const int nb = (c + 2) % 3;
            const int k0 = (c + 2) << 5;
            float* ab = As + nb * ASZ;
            float* bb = Bs + nb * BSZ;
#pragma unroll
            for (int it = 0; it < 4; ++it)
                cpa16(ab + (ar + it * 32) * ASTR + ac,
                      Ag0 + k0 + (size_t)(it * 32) * K);
#pragma unroll
            for (int it = 0; it < 4; ++it)
                cpa16(bb + (br + it * 8) * BSTR + bc,
                      Bg0 + (size_t)(k0 + it * 8) * N);
            cpa_commit();
        }

        const int cb = c % 3;
        const uint32_t* as = (const uint32_t*)(As + cb * ASZ);
        const uint32_t* bs = (const uint32_t*)(Bs + cb * BSZ);

#pragma unroll
        for (int kk = 0; kk < 32; kk += 8) {
            uint32_t af[2][4], bf[8][2];
#pragma unroll
            for (int mi = 0; mi < 2; ++mi) {
                const int mrow = (wm << 5) + (mi << 4) + lr;
                const uint32_t* ap = as + mrow * ASTR + kk + lc;
                af[mi][0] = ap[0];
                af[mi][1] = ap[8 * ASTR];
                af[mi][2] = ap[4];
                af[mi][3] = ap[8 * ASTR + 4];
            }
#pragma unroll
            for (int ni = 0; ni < 8; ++ni) {
                const int ncol = (wn << 6) + (ni << 3) + lr;
                const uint32_t* bp = bs + (kk + lc) * BSTR + ncol;
                bf[ni][0] = bp[0];
                bf[ni][1] = bp[4 * BSTR];
            }
#pragma unroll
            for (int mi = 0; mi < 2; ++mi)
#pragma unroll
                for (int ni = 0; ni < 8; ++ni)
                    MMA_TF32(acc[mi][ni], af[mi], bf[ni][0], bf[ni][1]);
        }
    }

#pragma unroll
    for (int mi = 0; mi < 2; ++mi) {
        const int row = row0 + (wm << 5) + (mi << 4) + lr;
#pragma unroll
        for (int ni = 0; ni < 8; ++ni) {
            const int col = col0 + (wn << 6) + (ni << 3) + (lc << 1);
            const float* cc = acc[mi][ni];
            if (CVTOUT) {
                *(uint2*)(C + (size_t)row * N + col) =
                    make_uint2(f2tf32(cc[0]), f2tf32(cc[1]));
                *(uint2*)(C + (size_t)(row + 8) * N + col) =
                    make_uint2(f2tf32(cc[2]), f2tf32(cc[3]));
            } else {
                *(float2*)(C + (size_t)row * N + col) =
                    make_float2(cc[0], cc[1]);
                *(float2*)(C + (size_t)(row + 8) * N + col) =
                    make_float2(cc[2], cc[3]);
            }
        }
    }
}

// ---------------------------------------------------------------------------
// Tensor-core causal flash attention (R10 config, unchanged):
// single-sync cp.async pipeline, Q frags in regs, exp2 softmax, deferred l.
// CTA = 128 q-rows x one head; 8 warps, 16-row stripes; 64-token K/V tiles.
// ---------------------------------------------------------------------------
#define KSTR 68
#define VSTR 72
#define PSTR 68
#define ATTN_SMEM ((128 * PSTR + 2 * 64 * KSTR + 2 * 64 * VSTR) * 4)  // 106496

__global__ __launch_bounds__(256, 2) void attn_tc(const float* __restrict__ qkv,
                                                  float* __restrict__ out)
{
    extern __shared__ float smm[];
    float* Ps = smm;                        // [128][PSTR]: Q staging, then P
    float* K0 = Ps + 128 * PSTR;
    float* K1 = K0 + 64 * KSTR;
    float* V0 = K1 + 64 * KSTR;
    float* V1 = V0 + 64 * VSTR;

    const int tid  = threadIdx.x;
    const int lane = tid & 31;
    const int warp = tid >> 5;
    const int lr   = lane >> 2;
    const int lc   = lane & 3;
    const int qb   = gridDim.x - 1 - blockIdx.x;   // heavy tiles first
    const int h    = blockIdx.y;
    const int b    = blockIdx.z;
    const int q0   = qb << 7;
    const int wrow = warp << 4;

    const float* bb = qkv + (size_t)b * (T_ * 3 * DM) + h * DH;

    const int fr  = tid >> 4;
    const int fc4 = (tid & 15) << 2;

    // prologue: stream tile 0 while we prep Q
    {
        const float* kg = bb + DM     + (size_t)fr * (3 * DM) + fc4;
        const float* vg = bb + 2 * DM + (size_t)fr * (3 * DM) + fc4;
#pragma unroll
        for (int it = 0; it < 4; ++it) {
            cpa16(K0 + (fr + it * 16) * KSTR + fc4,
                  kg + (size_t)(it * 16) * (3 * DM));
            cpa16(V0 + (fr + it * 16) * VSTR + fc4,
                  vg + (size_t)(it * 16) * (3 * DM));
        }
        cpa_commit();
    }

    const float QSCALE = 0.1803368867f;     // 0.125 * log2(e)
    for (int i = tid; i < 128 * 16; i += 256) {
        const int r  = i >> 4;
        const int c4 = (i & 15) << 2;
        float4 v = *(const float4*)(bb + (size_t)(q0 + r) * (3 * DM) + c4);
        v.x *= QSCALE; v.y *= QSCALE; v.z *= QSCALE; v.w *= QSCALE;
        *(uint4*)(Ps + r * PSTR + c4) = cvt4(v);
    }
    __syncthreads();

    uint32_t qf[8][4];
#pragma unroll
    for (int kkb = 0; kkb < 8; ++kkb) {
        const uint32_t* qp =
            (const uint32_t*)(Ps + (wrow + lr) * PSTR + kkb * 8 + lc);
        qf[kkb][0] = qp[0];
        qf[kkb][1] = qp[8 * PSTR];
        qf[kkb][2] = qp[4];
        qf[kkb][3] = qp[8 * PSTR + 4];
    }

    float m0 = -1e30f, m1 = -1e30f, l0 = 0.f, l1 = 0.f;   // l: per-lane partial
    float oacc[8][4];
#pragma unroll
    for (int ni = 0; ni < 8; ++ni)
#pragma unroll
        for (int r = 0; r < 4; ++r) oacc[ni][r] = 0.f;

    const int gr0 = q0 + wrow + lr;
    const int gr1 = gr0 + 8;
    const int nkt = 2 * qb + 2;

    for (int kt = 0; kt < nkt; ++kt) {
        const int cur = kt & 1;
        cpa_wait0();            // tile kt landed
        __syncthreads();        // publish tile kt; all reads of buf !cur done

        if (kt + 1 < nkt) {     // prefetch kt+1 into the other buffer
            float* Kn = (cur ? K0 : K1);
            float* Vn = (cur ? V0 : V1);
            const int kn0 = (kt + 1) << 6;
            const float* kg = bb + DM     + (size_t)(kn0 + fr) * (3 * DM) + fc4;
            const float* vg = bb + 2 * DM + (size_t)(kn0 + fr) * (3 * DM) + fc4;
#pragma unroll
            for (int it = 0; it < 4; ++it) {
                cpa16(Kn + (fr + it * 16) * KSTR + fc4,
                      kg + (size_t)(it * 16) * (3 * DM));
                cpa16(Vn + (fr + it * 16) * VSTR + fc4,
                      vg + (size_t)(it * 16) * (3 * DM));
            }
            cpa_commit();
        }

        const float* Ks = cur ? K1 : K0;
        const float* Vs = cur ? V1 : V0;

        // ---- S = Q @ K^T (16x64 per warp) ----
        float sacc[8][4];
#pragma unroll
        for (int ni = 0; ni < 8; ++ni)
#pragma unroll
            for (int r = 0; r < 4; ++r) sacc[ni][r] = 0.f;

#pragma unroll
        for (int kkb = 0; kkb < 8; ++kkb) {
#pragma unroll
            for (int ni = 0; ni < 8; ++ni) {
                const uint32_t* kp =
                    (const uint32_t*)(Ks + (ni * 8 + lr) * KSTR + kkb * 8 + lc);
                MMA_TF32(sacc[ni], qf[kkb], kp[0], kp[4]);
            }
        }

        // ---- causal mask ----
        if (kt >= 2 * qb) {
            const int k0 = kt << 6;
#pragma unroll
            for (int ni = 0; ni < 8; ++ni) {
                const int cb = k0 + ni * 8 + (lc << 1);
                if (cb     > gr0) sacc[ni][0] = -1e30f;
                if (cb + 1 > gr0) sacc[ni][1] = -1e30f;
                if (cb     > gr1) sacc[ni][2] = -1e30f;
                if (cb + 1 > gr1) sacc[ni][3] = -1e30f;
            }
        }

        // ---- online softmax in exp2 domain ----
        float rm0 = -1e30f, rm1 = -1e30f;
#pragma unroll
        for (int ni = 0; ni < 8; ++ni) {
            rm0 = fmaxf(rm0, fmaxf(sacc[ni][0], sacc[ni][1]));
            rm1 = fmaxf(rm1, fmaxf(sacc[ni][2], sacc[ni][3]));
        }
        rm0 = fmaxf(rm0, __shfl_xor_sync(0xffffffffu, rm0, 1, 4));
        rm0 = fmaxf(rm0, __shfl_xor_sync(0xffffffffu, rm0, 2, 4));
        rm1 = fmaxf(rm1, __shfl_xor_sync(0xffffffffu, rm1, 1, 4));
        rm1 = fmaxf(rm1, __shfl_xor_sync(0xffffffffu, rm1, 2, 4));

        const float mn0 = fmaxf(m0, rm0);
        const float mn1 = fmaxf(m1, rm1);
        const float c0f = ex2(m0 - mn0);
        const float c1f = ex2(m1 - mn1);
        m0 = mn0; m1 = mn1;

        float rs0 = 0.f, rs1 = 0.f;
#pragma unroll
        for (int ni = 0; ni < 8; ++ni) {
            sacc[ni][0] = ex2(sacc[ni][0] - mn0);
            sacc[ni][1] = ex2(sacc[ni][1] - mn0);
            sacc[ni][2] = ex2(sacc[ni][2] - mn1);
            sacc[ni][3] = ex2(sacc[ni][3] - mn1);
            rs0 += sacc[ni][0] + sacc[ni][1];
            rs1 += sacc[ni][2] + sacc[ni][3];
        }
        l0 = l0 * c0f + rs0;            // per-lane partial (quad-uniform c0f)
        l1 = l1 * c1f + rs1;
#pragma unroll
        for (int ni = 0; ni < 8; ++ni) {
            oacc[ni][0] *= c0f; oacc[ni][1] *= c0f;
            oacc[ni][2] *= c1f; oacc[ni][3] *= c1f;
        }

        // ---- stage P as tf32 (warp-private rows of Ps) ----
        {
            float* pr = Ps + (wrow + lr) * PSTR + (lc << 1);
#pragma unroll
            for (int ni = 0; ni < 8; ++ni) {
                *(uint2*)(pr + ni * 8) =
                    make_uint2(f2tf32(sacc[ni][0]), f2tf32(sacc[ni][1]));
                *(uint2*)(pr + 8 * PSTR + ni * 8) =
                    make_uint2(f2tf32(sacc[ni][2]), f2tf32(sacc[ni][3]));
            }
        }
        __syncwarp();

        // ---- O += P @ V ----
#pragma unroll
        for (int kkb = 0; kkb < 8; ++kkb) {
            uint32_t af[4];
            const uint32_t* pp =
                (const uint32_t*)(Ps + (wrow + lr) * PSTR + kkb * 8 + lc);
            af[0] = pp[0];
            af[1] = pp[8 * PSTR];
            af[2] = pp[4];
            af[3] = pp[8 * PSTR + 4];
#pragma unroll
            for (int ni = 0; ni < 8; ++ni) {
                const uint32_t* vp =
                    (const uint32_t*)(Vs + (kkb * 8 + lc) * VSTR + ni * 8 + lr);
                MMA_TF32(oacc[ni], af, vp[0], vp[4 * VSTR]);
            }
        }
    }

    // ---- epilogue: deferred l reduction, tf32-rounded output ----
    l0 += __shfl_xor_sync(0xffffffffu, l0, 1, 4);
    l0 += __shfl_xor_sync(0xffffffffu, l0, 2, 4);
    l1 += __shfl_xor_sync(0xffffffffu, l1, 1, 4);
    l1 += __shfl_xor_sync(0xffffffffu, l1, 2, 4);
    const float inv0 = 1.f / l0;
    const float inv1 = 1.f / l1;
    float* ob = out + (size_t)(b * T_ + gr0) * DM + h * DH + (lc << 1);
#pragma unroll
    for (int ni = 0; ni < 8; ++ni) {
        *(uint2*)(ob + ni * 8) =
            make_uint2(f2tf32(oacc[ni][0] * inv0), f2tf32(oacc[ni][1] * inv0));
        *(uint2*)(ob + (size_t)8 * DM + ni * 8) =
            make_uint2(f2tf32(oacc[ni][2] * inv1), f2tf32(oacc[ni][3] * inv1));
    }
}

// ---------------------------------------------------------------------------
extern "C" void kernel_launch(void* const* d_in, const int* in_sizes, int n_in,
                              void* d_out, int out_size)
{
    const float* x     = (const float*)d_in[0];
    const float* w_qkv = (const float*)d_in[1];
    const float* w_out = (const float*)d_in[2];
    float* out = (float*)d_out;

    float *qkv, *xa, *wq, *wo;
    cudaGetSymbolAddress((void**)&qkv, g_qkv);
    cudaGetSymbolAddress((void**)&xa,  g_xa);
    cudaGetSymbolAddress((void**)&wq,  g_wq);
    cudaGetSymbolAddress((void**)&wo,  g_wo);

    cudaFuncSetAttribute(tf32_gemm<true>,
                         cudaFuncAttributeMaxDynamicSharedMemorySize, GEMM_SMEM);
    cudaFuncSetAttribute(tf32_gemm<false>,
                         cudaFuncAttributeMaxDynamicSharedMemorySize, GEMM_SMEM);
    cudaFuncSetAttribute(attn_tc,
                         cudaFuncAttributeMaxDynamicSharedMemorySize, ATTN_SMEM);

    // 0) pre-round inputs to tf32 bit patterns
    cvt_tf32<<<(NTOK * DM) / 1024, 256>>>((const float4*)x,       (uint4*)xa);
    cvt_tf32<<<(DM * 3 * DM) / 1024, 256>>>((const float4*)w_qkv, (uint4*)wq);
    cvt_tf32<<<(DM * DM) / 1024, 256>>>((const float4*)w_out,     (uint4*)wo);

    // 1) qkv = x @ w_qkv  (3-stage pipelined; epilogue rounds to tf32)
    tf32_gemm<true><<<dim3((3 * DM) / 128, NTOK / 128), 256, GEMM_SMEM>>>(
        xa, wq, qkv, NTOK, 3 * DM, DM);
    // 2) causal flash attention (writes tf32 into xa)
    attn_tc<<<dim3(T_ / 128, H_, B_), 256, ATTN_SMEM>>>(qkv, xa);
    // 3) out = attn @ w_out  (final fp32 output)
    tf32_gemm<false><<<dim3(DM / 128, NTOK / 128), 256, GEMM_SMEM>>>(
        xa, wo, out, NTOK, DM, DM);
}

// round 13
// speedup vs baseline: 1.2810x; 1.2810x over previous
#include <cuda_runtime.h>
#include <cuda_fp16.h>
#include <cstdint>
#include <cstddef>

#define B_   4
#define T_   2048
#define DM   1024
#define H_   16
#define DH   64
#define NTOK (B_ * T_)   // 8192

// Scratch (allocation-free rule: __device__ globals)
__device__ float  g_qkv [(size_t)NTOK * 3 * DM];   // tf32-rounded qkv (fp32)
__device__ __half g_x16 [(size_t)NTOK * DM];       // half(x), later half(attn out)
__device__ __half g_wq16[(size_t)3 * DM * DM];     // half(w_qkv^T) [3072][1024]
__device__ __half g_wo16[(size_t)DM * DM];         // half(w_out^T) [1024][1024]

__device__ __forceinline__ void cpa16(const void* s, const void* g) {
    uint32_t sa = (uint32_t)__cvta_generic_to_shared(s);
    asm volatile("cp.async.cg.shared.global [%0], [%1], 16;\n" :: "r"(sa), "l"(g));
}
__device__ __forceinline__ void cpa_commit() {
    asm volatile("cp.async.commit_group;\n");
}
__device__ __forceinline__ void cpa_wait0() {
    asm volatile("cp.async.wait_group 0;\n");
}
__device__ __forceinline__ uint32_t f2tf32(float x) {
    uint32_t r;
    asm("cvt.rna.tf32.f32 %0, %1;" : "=r"(r) : "f"(x));
    return r;
}
__device__ __forceinline__ uint4 cvt4(float4 v) {
    uint4 u;
    u.x = f2tf32(v.x); u.y = f2tf32(v.y);
    u.z = f2tf32(v.z); u.w = f2tf32(v.w);
    return u;
}
__device__ __forceinline__ float ex2(float x) {
    float r;
    asm("ex2.approx.f32 %0, %1;" : "=f"(r) : "f"(x));
    return r;
}
// tf32 MMA (attention, unchanged)
#define MMA_TF32(CC, AF, B0, B1)                                              \
    asm volatile(                                                             \
        "mma.sync.aligned.m16n8k8.row.col.f32.tf32.tf32.f32 "                 \
        "{%0,%1,%2,%3}, {%4,%5,%6,%7}, {%8,%9}, {%0,%1,%2,%3};"               \
        : "+f"((CC)[0]), "+f"((CC)[1]), "+f"((CC)[2]), "+f"((CC)[3])          \
        : "r"((AF)[0]), "r"((AF)[1]), "r"((AF)[2]), "r"((AF)[3]),             \
          "r"(B0), "r"(B1))
// fp16 MMA (GEMMs)
#define MMA_F16(CC, AF, B0, B1)                                               \
    asm volatile(                                                             \
        "mma.sync.aligned.m16n8k16.row.col.f32.f16.f16.f32 "                  \
        "{%0,%1,%2,%3}, {%4,%5,%6,%7}, {%8,%9}, {%0,%1,%2,%3};"               \
        : "+f"((CC)[0]), "+f"((CC)[1]), "+f"((CC)[2]), "+f"((CC)[3])          \
        : "r"((AF)[0]), "r"((AF)[1]), "r"((AF)[2]), "r"((AF)[3]),             \
          "r"(B0), "r"(B1))

// ---------------------------------------------------------------------------
// Pre-passes.
// ---------------------------------------------------------------------------
// fp32 -> fp16 elementwise
__global__ __launch_bounds__(256) void cvt_h(const float4* __restrict__ in,
                                             uint2* __restrict__ out)
{
    const size_t i = (size_t)blockIdx.x * 256 + threadIdx.x;
    const float4 v = in[i];
    const __half2 lo = __floats2half2_rn(v.x, v.y);
    const __half2 hi = __floats2half2_rn(v.z, v.w);
    out[i] = make_uint2(*(const uint32_t*)&lo, *(const uint32_t*)&hi);
}
// fp32 [R][Cc] -> fp16 [Cc][R] (transpose)
__global__ __launch_bounds__(256) void cvt_ht(const float* __restrict__ in,
                                              __half* __restrict__ out,
                                              int R, int Cc)
{
    __shared__ float t[32][33];
    const int tx = threadIdx.x & 31, ty = threadIdx.x >> 5;   // 32x8
    const int c0 = blockIdx.x << 5, r0 = blockIdx.y << 5;
#pragma unroll
    for (int i = 0; i < 32; i += 8)
        t[ty + i][tx] = in[(size_t)(r0 + ty + i) * Cc + c0 + tx];
    __syncthreads();
#pragma unroll
    for (int i = 0; i < 32; i += 8)
        out[(size_t)(c0 + ty + i) * R + r0 + tx] = __float2half_rn(t[tx][ty + i]);
}

// ---------------------------------------------------------------------------
// FP16 tensor-core GEMM: C[M,N] = A[M,K]h @ Bt[N,K]h^T  (m16n8k16, fp32 acc).
// 128x128 CTA tile, k-chunk 32, 256 threads (8 warps, warp tile 32x64),
// cp.async double buffer. A/B smem: [128][40] halves (stride 40 -> banks
// (20*lr+lc)%32, conflict-free). Half the bytes + 2x MMA rate vs tf32.
// CVTOUT: epilogue rounds C to tf32 fp32 (qkv for attention); else plain fp32.
// ---------------------------------------------------------------------------
#define HSTR 40
#define HSZ  (128 * HSTR)                  // halves per tile
#define HGEMM_SMEM (4 * HSZ * 2)           // 2 bufs x (A+B) x 2B = 40960

template<bool CVTOUT>
__global__ __launch_bounds__(256) void hgemm(const __half* __restrict__ A,
                                             const __half* __restrict__ Bt,
                                             float* __restrict__ C,
                                             int M, int N, int K)
{
    extern __shared__ __half smh[];
    __half* As = smh;                      // [2][128][HSTR]
    __half* Bs = smh + 2 * HSZ;            // [2][128][HSTR]

    const int tid  = threadIdx.x;
    const int lane = tid & 31;
    const int warp = tid >> 5;
    const int wm   = warp >> 1;            // 0..3 (32-row blocks)
    const int wn   = warp & 1;             // 0..1 (64-col blocks)
    const int lr   = lane >> 2;
    const int lc   = lane & 3;
    const int row0 = blockIdx.y << 7;
    const int col0 = blockIdx.x << 7;

    // fill indices: 128 rows x 4 chunks of 16B (8 halves); 2 passes of 64 rows
    const int frow = tid >> 2;             // 0..63 (+64)
    const int fch  = (tid & 3) << 3;       // half offset 0,8,16,24

    const __half* Ag = A  + (size_t)(row0 + frow) * K + fch;
    const __half* Bg = Bt + (size_t)(col0 + frow) * K + fch;

    float acc[2][8][4];
#pragma unroll
    for (int mi = 0; mi < 2; ++mi)
#pragma unroll
        for (int ni = 0; ni < 8; ++ni)
#pragma unroll
            for (int r = 0; r < 4; ++r) acc[mi][ni][r] = 0.f;

    const int nch = K >> 5;
    // prologue: chunk 0 -> buffer 0
#pragma unroll
    for (int p = 0; p < 2; ++p) {
        cpa16(As + (frow + p * 64) * HSTR + fch, Ag + (size_t)(p * 64) * K);
        cpa16(Bs + (frow + p * 64) * HSTR + fch, Bg + (size_t)(p * 64) * K);
    }
    cpa_commit();

    for (int c = 0; c < nch; ++c) {
        cpa_wait0();
        __syncthreads();

        const int cb = c & 1;
        if (c + 1 < nch) {
            const int k0 = (c + 1) << 5;
            __half* an = As + ((c + 1) & 1) * HSZ;
            __half* bn = Bs + ((c + 1) & 1) * HSZ;
#pragma unroll
            for (int p = 0; p < 2; ++p) {
                cpa16(an + (frow + p * 64) * HSTR + fch,
                      Ag + k0 + (size_t)(p * 64) * K);
                cpa16(bn + (frow + p * 64) * HSTR + fch,
                      Bg + k0 + (size_t)(p * 64) * K);
            }
            cpa_commit();
        }

        const uint32_t* as = (const uint32_t*)(As + cb * HSZ);
        const uint32_t* bs = (const uint32_t*)(Bs + cb * HSZ);

#pragma unroll
        for (int kk2 = 0; kk2 < 16; kk2 += 8) {     // two k16 steps (u32 units)
            uint32_t af[2][4], bf[8][2];
#pragma unroll
            for (int mi = 0; mi < 2; ++mi) {
                const int mrow = (wm << 5) + (mi << 4) + lr;
                const uint32_t* ap = as + mrow * (HSTR / 2) + kk2 + lc;
                af[mi][0] = ap[0];                   // (row,   k 2lc..2lc+1)
                af[mi][1] = ap[8 * (HSTR / 2)];      // (row+8, same k)
                af[mi][2] = ap[4];                   // (row,   k+8)
                af[mi][3] = ap[8 * (HSTR / 2) + 4];  // (row+8, k+8)
            }
#pragma unroll
            for (int ni = 0; ni < 8; ++ni) {
                const int ncol = (wn << 6) + (ni << 3) + lr;
                const uint32_t* bp = bs + ncol * (HSTR / 2) + kk2 + lc;
                bf[ni][0] = bp[0];                   // (n, k 2lc..2lc+1)
                bf[ni][1] = bp[4];                   // (n, k+8)
            }
#pragma unroll
            for (int mi = 0; mi < 2; ++mi)
#pragma unroll
                for (int ni = 0; ni < 8; ++ni)
                    MMA_F16(acc[mi][ni], af[mi], bf[ni][0], bf[ni][1]);
        }
    }

#pragma unroll
    for (int mi = 0; mi < 2; ++mi) {
        const int row = row0 + (wm << 5) + (mi << 4) + lr;
#pragma unroll
        for (int ni = 0; ni < 8; ++ni) {
            const int col = col0 + (wn << 6) + (ni << 3) + (lc << 1);
            const float* cc = acc[mi][ni];
            if (CVTOUT) {
                *(uint2*)(C + (size_t)row * N + col) =
                    make_uint2(f2tf32(cc[0]), f2tf32(cc[1]));
                *(uint2*)(C + (size_t)(row + 8) * N + col) =
                    make_uint2(f2tf32(cc[2]), f2tf32(cc[3]));
            } else {
                *(float2*)(C + (size_t)row * N + col) =
                    make_float2(cc[0], cc[1]);
                *(float2*)(C + (size_t)(row + 8) * N + col) =
                    make_float2(cc[2], cc[3]);
            }
        }
    }
}

// ---------------------------------------------------------------------------
// Tensor-core causal flash attention (R10 755us config; only the epilogue
// changed: writes fp16 for the fp16 out-projection).
// ---------------------------------------------------------------------------
#define KSTR 68
#define VSTR 72
#define PSTR 68
#define ATTN_SMEM ((128 * PSTR + 2 * 64 * KSTR + 2 * 64 * VSTR) * 4)  // 106496

__global__ __launch_bounds__(256, 2) void attn_tc(const float* __restrict__ qkv,
                                                  __half* __restrict__ out)
{
    extern __shared__ float smm[];
    float* Ps = smm;                        // [128][PSTR]: Q staging, then P
    float* K0 = Ps + 128 * PSTR;
    float* K1 = K0 + 64 * KSTR;
    float* V0 = K1 + 64 * KSTR;
    float* V1 = V0 + 64 * VSTR;

    const int tid  = threadIdx.x;
    const int lane = tid & 31;
    const int warp = tid >> 5;
    const int lr   = lane >> 2;
    const int lc   = lane & 3;
    const int qb   = gridDim.x - 1 - blockIdx.x;   // heavy tiles first
    const int h    = blockIdx.y;
    const int b    = blockIdx.z;
    const int q0   = qb << 7;
    const int wrow = warp << 4;

    const float* bb = qkv + (size_t)b * (T_ * 3 * DM) + h * DH;

    const int fr  = tid >> 4;
    const int fc4 = (tid & 15) << 2;

    {
        const float* kg = bb + DM     + (size_t)fr * (3 * DM) + fc4;
        const float* vg = bb + 2 * DM + (size_t)fr * (3 * DM) + fc4;
#pragma unroll
        for (int it = 0; it < 4; ++it) {
            cpa16(K0 + (fr + it * 16) * KSTR + fc4,
                  kg + (size_t)(it * 16) * (3 * DM));
            cpa16(V0 + (fr + it * 16) * VSTR + fc4,
                  vg + (size_t)(it * 16) * (3 * DM));
        }
        cpa_commit();
    }

    const float QSCALE = 0.1803368867f;     // 0.125 * log2(e)
    for (int i = tid; i < 128 * 16; i += 256) {
        const int r  = i >> 4;
        const int c4 = (i & 15) << 2;
        float4 v = *(const float4*)(bb + (size_t)(q0 + r) * (3 * DM) + c4);
        v.x *= QSCALE; v.y *= QSCALE; v.z *= QSCALE; v.w *= QSCALE;
        *(uint4*)(Ps + r * PSTR + c4) = cvt4(v);
    }
    __syncthreads();

    uint32_t qf[8][4];
#pragma unroll
    for (int kkb = 0; kkb < 8; ++kkb) {
        const uint32_t* qp =
            (const uint32_t*)(Ps + (wrow + lr) * PSTR + kkb * 8 + lc);
        qf[kkb][0] = qp[0];
        qf[kkb][1] = qp[8 * PSTR];
        qf[kkb][2] = qp[4];
        qf[kkb][3] = qp[8 * PSTR + 4];
    }

    float m0 = -1e30f, m1 = -1e30f, l0 = 0.f, l1 = 0.f;
    float oacc[8][4];
#pragma unroll
    for (int ni = 0; ni < 8; ++ni)
#pragma unroll
        for (int r = 0; r < 4; ++r) oacc[ni][r] = 0.f;

    const int gr0 = q0 + wrow + lr;
    const int gr1 = gr0 + 8;
    const int nkt = 2 * qb + 2;

    for (int kt = 0; kt < nkt; ++kt) {
        const int cur = kt & 1;
        cpa_wait0();
        __syncthreads();

        if (kt + 1 < nkt) {
            float* Kn = (cur ? K0 : K1);
            float* Vn = (cur ? V0 : V1);
            const int kn0 = (kt + 1) << 6;
            const float* kg = bb + DM     + (size_t)(kn0 + fr) * (3 * DM) + fc4;
            const float* vg = bb + 2 * DM + (size_t)(kn0 + fr) * (3 * DM) + fc4;
#pragma unroll
            for (int it = 0; it < 4; ++it) {
                cpa16(Kn + (fr + it * 16) * KSTR + fc4,
                      kg + (size_t)(it * 16) * (3 * DM));
                cpa16(Vn + (fr + it * 16) * VSTR + fc4,
                      vg + (size_t)(it * 16) * (3 * DM));
            }
            cpa_commit();
        }

        const float* Ks = cur ? K1 : K0;
        const float* Vs = cur ? V1 : V0;

        float sacc[8][4];
#pragma unroll
        for (int ni = 0; ni < 8; ++ni)
#pragma unroll
            for (int r = 0; r < 4; ++r) sacc[ni][r] = 0.f;

#pragma unroll
        for (int kkb = 0; kkb < 8; ++kkb) {
#pragma unroll
            for (int ni = 0; ni < 8; ++ni) {
                const uint32_t* kp =
                    (const uint32_t*)(Ks + (ni * 8 + lr) * KSTR + kkb * 8 + lc);
                MMA_TF32(sacc[ni], qf[kkb], kp[0], kp[4]);
            }
        }

        if (kt >= 2 * qb) {
            const int k0 = kt << 6;
#pragma unroll
            for (int ni = 0; ni < 8; ++ni) {
                const int cb = k0 + ni * 8 + (lc << 1);
                if (cb     > gr0) sacc[ni][0] = -1e30f;
                if (cb + 1 > gr0) sacc[ni][1] = -1e30f;
                if (cb     > gr1) sacc[ni][2] = -1e30f;
                if (cb + 1 > gr1) sacc[ni][3] = -1e30f;
            }
        }

        float rm0 = -1e30f, rm1 = -1e30f;
#pragma unroll
        for (int ni = 0; ni < 8; ++ni) {
            rm0 = fmaxf(rm0, fmaxf(sacc[ni][0], sacc[ni][1]));
            rm1 = fmaxf(rm1, fmaxf(sacc[ni][2], sacc[ni][3]));
        }
        rm0 = fmaxf(rm0, __shfl_xor_sync(0xffffffffu, rm0, 1, 4));
        rm0 = fmaxf(rm0, __shfl_xor_sync(0xffffffffu, rm0, 2, 4));
        rm1 = fmaxf(rm1, __shfl_xor_sync(0xffffffffu, rm1, 1, 4));
        rm1 = fmaxf(rm1, __shfl_xor_sync(0xffffffffu, rm1, 2, 4));

        const float mn0 = fmaxf(m0, rm0);
        const float mn1 = fmaxf(m1, rm1);
        const float c0f = ex2(m0 - mn0);
        const float c1f = ex2(m1 - mn1);
        m0 = mn0; m1 = mn1;

        float rs0 = 0.f, rs1 = 0.f;
#pragma unroll
        for (int ni = 0; ni < 8; ++ni) {
            sacc[ni][0] = ex2(sacc[ni][0] - mn0);
            sacc[ni][1] = ex2(sacc[ni][1] - mn0);
            sacc[ni][2] = ex2(sacc[ni][2] - mn1);
            sacc[ni][3] = ex2(sacc[ni][3] - mn1);
            rs0 += sacc[ni][0] + sacc[ni][1];
            rs1 += sacc[ni][2] + sacc[ni][3];
        }
        l0 = l0 * c0f + rs0;
        l1 = l1 * c1f + rs1;
#pragma unroll
        for (int ni = 0; ni < 8; ++ni) {
            oacc[ni][0] *= c0f; oacc[ni][1] *= c0f;
            oacc[ni][2] *= c1f; oacc[ni][3] *= c1f;
        }

        {
            float* pr = Ps + (wrow + lr) * PSTR + (lc << 1);
#pragma unroll
            for (int ni = 0; ni < 8; ++ni) {
                *(uint2*)(pr + ni * 8) =
                    make_uint2(f2tf32(sacc[ni][0]), f2tf32(sacc[ni][1]));
                *(uint2*)(pr + 8 * PSTR + ni * 8) =
                    make_uint2(f2tf32(sacc[ni][2]), f2tf32(sacc[ni][3]));
            }
        }
        __syncwarp();

#pragma unroll
        for (int kkb = 0; kkb < 8; ++kkb) {
            uint32_t af[4];
            const uint32_t* pp =
                (const uint32_t*)(Ps + (wrow + lr) * PSTR + kkb * 8 + lc);
            af[0] = pp[0];
            af[1] = pp[8 * PSTR];
            af[2] = pp[4];
            af[3] = pp[8 * PSTR + 4];
#pragma unroll
            for (int ni = 0; ni < 8; ++ni) {
                const uint32_t* vp =
                    (const uint32_t*)(Vs + (kkb * 8 + lc) * VSTR + ni * 8 + lr);
                MMA_TF32(oacc[ni], af, vp[0], vp[4 * VSTR]);
            }
        }
    }

    // epilogue: deferred l reduction; write fp16 (feeds fp16 out-projection)
    l0 += __shfl_xor_sync(0xffffffffu, l0, 1, 4);
    l0 += __shfl_xor_sync(0xffffffffu, l0, 2, 4);
    l1 += __shfl_xor_sync(0xffffffffu, l1, 1, 4);
    l1 += __shfl_xor_sync(0xffffffffu, l1, 2, 4);
    const float inv0 = 1.f / l0;
    const float inv1 = 1.f / l1;
    __half* ob = out + (size_t)(b * T_ + gr0) * DM + h * DH + (lc << 1);
#pragma unroll
    for (int ni = 0; ni < 8; ++ni) {
        *(__half2*)(ob + ni * 8) =
            __floats2half2_rn(oacc[ni][0] * inv0, oacc[ni][1] * inv0);
        *(__half2*)(ob + (size_t)8 * DM + ni * 8) =
            __floats2half2_rn(oacc[ni][2] * inv1, oacc[ni][3] * inv1);
    }
}

// ---------------------------------------------------------------------------
extern "C" void kernel_launch(void* const* d_in, const int* in_sizes, int n_in,
                              void* d_out, int out_size)
{
    const float* x     = (const float*)d_in[0];
    const float* w_qkv = (const float*)d_in[1];
    const float* w_out = (const float*)d_in[2];
    float* out = (float*)d_out;

    float* qkv;
    __half *x16, *wq16, *wo16;
    cudaGetSymbolAddress((void**)&qkv,  g_qkv);
    cudaGetSymbolAddress((void**)&x16,  g_x16);
    cudaGetSymbolAddress((void**)&wq16, g_wq16);
    cudaGetSymbolAddress((void**)&wo16, g_wo16);

    cudaFuncSetAttribute(hgemm<true>,
                         cudaFuncAttributeMaxDynamicSharedMemorySize, HGEMM_SMEM);
    cudaFuncSetAttribute(hgemm<false>,
                         cudaFuncAttributeMaxDynamicSharedMemorySize, HGEMM_SMEM);
    cudaFuncSetAttribute(attn_tc,
                         cudaFuncAttributeMaxDynamicSharedMemorySize, ATTN_SMEM);

    // 0) prepasses: x -> fp16; weights -> fp16 transposed [N][K]
    cvt_h<<<(NTOK * DM) / 1024, 256>>>((const float4*)x, (uint2*)x16);
    cvt_ht<<<dim3((3 * DM) / 32, DM / 32), 256>>>(w_qkv, wq16, DM, 3 * DM);
    cvt_ht<<<dim3(DM / 32, DM / 32), 256>>>(w_out, wo16, DM, DM);

    // 1) qkv = x @ w_qkv  (fp16 MMA; epilogue rounds to tf32 fp32)
    hgemm<true><<<dim3((3 * DM) / 128, NTOK / 128), 256, HGEMM_SMEM>>>(
        x16, wq16, qkv, NTOK, 3 * DM, DM);
    // 2) causal flash attention (unchanged; writes fp16 into x16)
    attn_tc<<<dim3(T_ / 128, H_, B_), 256, ATTN_SMEM>>>(qkv, x16);
    // 3) out = attn @ w_out  (fp16 MMA; final fp32 output)
    hgemm<false><<<dim3(DM / 128, NTOK / 128), 256, HGEMM_SMEM>>>(
        x16, wo16, out, NTOK, DM, DM);
}

// round 14
// speedup vs baseline: 1.6825x; 1.3134x over previous
#include <cuda_runtime.h>
#include <cuda_fp16.h>
#include <cstdint>
#include <cstddef>

#define B_   4
#define T_   2048
#define DM   1024
#define H_   16
#define DH   64
#define NTOK (B_ * T_)   // 8192
#define TD3  (3 * DM)

// Scratch (allocation-free rule: __device__ globals)
__device__ __half g_qkv16[(size_t)NTOK * 3 * DM];  // half qkv
__device__ __half g_x16 [(size_t)NTOK * DM];       // half(x), later half(attn out)
__device__ __half g_wq16[(size_t)3 * DM * DM];     // half(w_qkv^T) [3072][1024]
__device__ __half g_wo16[(size_t)DM * DM];         // half(w_out^T) [1024][1024]

__device__ __forceinline__ void cpa16(const void* s, const void* g) {
    uint32_t sa = (uint32_t)__cvta_generic_to_shared(s);
    asm volatile("cp.async.cg.shared.global [%0], [%1], 16;\n" :: "r"(sa), "l"(g));
}
__device__ __forceinline__ void cpa_commit() {
    asm volatile("cp.async.commit_group;\n");
}
__device__ __forceinline__ void cpa_wait0() {
    asm volatile("cp.async.wait_group 0;\n");
}
__device__ __forceinline__ float ex2(float x) {
    float r;
    asm("ex2.approx.f32 %0, %1;" : "=f"(r) : "f"(x));
    return r;
}
__device__ __forceinline__ uint32_t smem_u32(const void* p) {
    uint32_t a;
    asm("{ .reg .u64 t; cvta.to.shared.u64 t, %1; cvt.u32.u64 %0, t; }"
        : "=r"(a) : "l"(p));
    return a;
}
__device__ __forceinline__ void ldsm2(uint32_t& r0, uint32_t& r1, uint32_t a) {
    asm volatile("ldmatrix.sync.aligned.m8n8.x2.shared.b16 {%0,%1}, [%2];"
                 : "=r"(r0), "=r"(r1) : "r"(a));
}
__device__ __forceinline__ void ldsm2t(uint32_t& r0, uint32_t& r1, uint32_t a) {
    asm volatile("ldmatrix.sync.aligned.m8n8.x2.trans.shared.b16 {%0,%1}, [%2];"
                 : "=r"(r0), "=r"(r1) : "r"(a));
}
// fp16 MMA m16n8k16 (fp32 acc)
#define MMA_F16(CC, AF, B0, B1)                                               \
    asm volatile(                                                             \
        "mma.sync.aligned.m16n8k16.row.col.f32.f16.f16.f32 "                  \
        "{%0,%1,%2,%3}, {%4,%5,%6,%7}, {%8,%9}, {%0,%1,%2,%3};"               \
        : "+f"((CC)[0]), "+f"((CC)[1]), "+f"((CC)[2]), "+f"((CC)[3])          \
        : "r"((AF)[0]), "r"((AF)[1]), "r"((AF)[2]), "r"((AF)[3]),             \
          "r"(B0), "r"(B1))

// ---------------------------------------------------------------------------
// Pre-passes.
// ---------------------------------------------------------------------------
__global__ __launch_bounds__(256) void cvt_h(const float4* __restrict__ in,
                                             uint2* __restrict__ out)
{
    const size_t i = (size_t)blockIdx.x * 256 + threadIdx.x;
    const float4 v = in[i];
    const __half2 lo = __floats2half2_rn(v.x, v.y);
    const __half2 hi = __floats2half2_rn(v.z, v.w);
    out[i] = make_uint2(*(const uint32_t*)&lo, *(const uint32_t*)&hi);
}
__global__ __launch_bounds__(256) void cvt_ht(const float* __restrict__ in,
                                              __half* __restrict__ out,
                                              int R, int Cc)
{
    __shared__ float t[32][33];
    const int tx = threadIdx.x & 31, ty = threadIdx.x >> 5;
    const int c0 = blockIdx.x << 5, r0 = blockIdx.y << 5;
#pragma unroll
    for (int i = 0; i < 32; i += 8)
        t[ty + i][tx] = in[(size_t)(r0 + ty + i) * Cc + c0 + tx];
    __syncthreads();
#pragma unroll
    for (int i = 0; i < 32; i += 8)
        out[(size_t)(c0 + ty + i) * R + r0 + tx] = __float2half_rn(t[tx][ty + i]);
}

// ---------------------------------------------------------------------------
// FP16 GEMM (R13 structure). OM=1: fp16 output; OM=0: fp32 output.
// ---------------------------------------------------------------------------
#define HSTR 40
#define HSZ  (128 * HSTR)
#define HGEMM_SMEM (4 * HSZ * 2)           // 40960 bytes

template<int OM>
__global__ __launch_bounds__(256) void hgemm(const __half* __restrict__ A,
                                             const __half* __restrict__ Bt,
                                             void* __restrict__ Cv,
                                             int M, int N, int K)
{
    extern __shared__ __half smh[];
    __half* As = smh;
    __half* Bs = smh + 2 * HSZ;

    const int tid  = threadIdx.x;
    const int lane = tid & 31;
    const int warp = tid >> 5;
    const int wm   = warp >> 1;
    const int wn   = warp & 1;
    const int lr   = lane >> 2;
    const int lc   = lane & 3;
    const int row0 = blockIdx.y << 7;
    const int col0 = blockIdx.x << 7;

    const int frow = tid >> 2;
    const int fch  = (tid & 3) << 3;

    const __half* Ag = A  + (size_t)(row0 + frow) * K + fch;
    const __half* Bg = Bt + (size_t)(col0 + frow) * K + fch;

    float acc[2][8][4];
#pragma unroll
    for (int mi = 0; mi < 2; ++mi)
#pragma unroll
        for (int ni = 0; ni < 8; ++ni)
#pragma unroll
            for (int r = 0; r < 4; ++r) acc[mi][ni][r] = 0.f;

    const int nch = K >> 5;
#pragma unroll
    for (int p = 0; p < 2; ++p) {
        cpa16(As + (frow + p * 64) * HSTR + fch, Ag + (size_t)(p * 64) * K);
        cpa16(Bs + (frow + p * 64) * HSTR + fch, Bg + (size_t)(p * 64) * K);
    }
    cpa_commit();

    for (int c = 0; c < nch; ++c) {
        cpa_wait0();
        __syncthreads();

        const int cb = c & 1;
        if (c + 1 < nch) {
            const int k0 = (c + 1) << 5;
            __half* an = As + ((c + 1) & 1) * HSZ;
            __half* bn = Bs + ((c + 1) & 1) * HSZ;
#pragma unroll
            for (int p = 0; p < 2; ++p) {
                cpa16(an + (frow + p * 64) * HSTR + fch,
                      Ag + k0 + (size_t)(p * 64) * K);
                cpa16(bn + (frow + p * 64) * HSTR + fch,
                      Bg + k0 + (size_t)(p * 64) * K);
            }
            cpa_commit();
        }

        const uint32_t* as = (const uint32_t*)(As + cb * HSZ);
        const uint32_t* bs = (const uint32_t*)(Bs + cb * HSZ);

#pragma unroll
        for (int kk2 = 0; kk2 < 16; kk2 += 8) {
            uint32_t af[2][4], bf[8][2];
#pragma unroll
            for (int mi = 0; mi < 2; ++mi) {
                const int mrow = (wm << 5) + (mi << 4) + lr;
                const uint32_t* ap = as + mrow * (HSTR / 2) + kk2 + lc;
                af[mi][0] = ap[0];
                af[mi][1] = ap[8 * (HSTR / 2)];
                af[mi][2] = ap[4];
                af[mi][3] = ap[8 * (HSTR / 2) + 4];
            }
#pragma unroll
            for (int ni = 0; ni < 8; ++ni) {
                const int ncol = (wn << 6) + (ni << 3) + lr;
                const uint32_t* bp = bs + ncol * (HSTR / 2) + kk2 + lc;
                bf[ni][0] = bp[0];
                bf[ni][1] = bp[4];
            }
#pragma unroll
            for (int mi = 0; mi < 2; ++mi)
#pragma unroll
                for (int ni = 0; ni < 8; ++ni)
                    MMA_F16(acc[mi][ni], af[mi], bf[ni][0], bf[ni][1]);
        }
    }

#pragma unroll
    for (int mi = 0; mi < 2; ++mi) {
        const int row = row0 + (wm << 5) + (mi << 4) + lr;
#pragma unroll
        for (int ni = 0; ni < 8; ++ni) {
            const int col = col0 + (wn << 6) + (ni << 3) + (lc << 1);
            const float* cc = acc[mi][ni];
            if (OM == 1) {
                __half* Ch = (__half*)Cv;
                *(__half2*)(Ch + (size_t)row * N + col) =
                    __floats2half2_rn(cc[0], cc[1]);
                *(__half2*)(Ch + (size_t)(row + 8) * N + col) =
                    __floats2half2_rn(cc[2], cc[3]);
            } else {
                float* Cf = (float*)Cv;
                *(float2*)(Cf + (size_t)row * N + col) =
                    make_float2(cc[0], cc[1]);
                *(float2*)(Cf + (size_t)(row + 8) * N + col) =
                    make_float2(cc[2], cc[3]);
            }
        }
    }
}

// ---------------------------------------------------------------------------
// FP16 tensor-core causal flash attention:
// - qkv in fp16; m16n8k16 MMAs for S and P@V (2x tensor rate, half LDS bytes).
// - K B-frags: ldmatrix.x2 (non-trans) on row-major K[token][dim].
// - V B-frags: ldmatrix.x2.trans on row-major V[token][dim].
// - Q frags in regs (16); P staged fp16 (C-frag pairs == A-frag pairs).
// - R10 pipeline: cp.async double-buffer, single sync/tile, exp2 softmax,
//   deferred l-reduction. smem 55296 B, 2 CTAs/SM.
// ---------------------------------------------------------------------------
#define AH_STR 72                                  // halves per row (36 u32)
#define ATTN_SMEM ((128 * AH_STR + 4 * 64 * AH_STR) * 2)   // 55296 B

__global__ __launch_bounds__(256, 2) void attn_h(const __half* __restrict__ qkv,
                                                 __half* __restrict__ out)
{
    extern __shared__ __half smh2[];
    __half* Ps = smh2;                      // [128][72]: Q staging, then P
    __half* K0 = Ps + 128 * AH_STR;
    __half* K1 = K0 + 64 * AH_STR;
    __half* V0 = K1 + 64 * AH_STR;
    __half* V1 = V0 + 64 * AH_STR;

    const int tid  = threadIdx.x;
    const int lane = tid & 31;
    const int warp = tid >> 5;
    const int lr   = lane >> 2;
    const int lc   = lane & 3;
    const int qb   = gridDim.x - 1 - blockIdx.x;   // heavy tiles first
    const int h    = blockIdx.y;
    const int b    = blockIdx.z;
    const int q0   = qb << 7;
    const int wrow = warp << 4;

    const __half* bb = qkv + (size_t)b * (T_ * TD3) + h * DH;

    // K/V fill indices: 64 rows x 8 chunks of 16B, 2 passes of 32 rows
    const int fr   = tid >> 3;              // 0..31
    const int fseg = (tid & 7) << 3;        // half offset 0,8,...,56

    // prologue: stream tile 0
#pragma unroll
    for (int p = 0; p < 2; ++p) {
        const int row = fr + p * 32;
        cpa16(K0 + row * AH_STR + fseg, bb + DM     + (size_t)row * TD3 + fseg);
        cpa16(V0 + row * AH_STR + fseg, bb + 2 * DM + (size_t)row * TD3 + fseg);
    }
    cpa_commit();

    // Q tile: load fp16, scale by 0.125*log2(e) in half2, store to Ps
    const __half2 qs2 = __float2half2_rn(0.1803368867f);
    for (int i = tid; i < 128 * 8; i += 256) {
        const int r  = i >> 3;
        const int c8 = (i & 7) << 3;
        uint4 v = *(const uint4*)(bb + (size_t)(q0 + r) * TD3 + c8);
        __half2* hp = (__half2*)&v;
        hp[0] = __hmul2(hp[0], qs2);
        hp[1] = __hmul2(hp[1], qs2);
        hp[2] = __hmul2(hp[2], qs2);
        hp[3] = __hmul2(hp[3], qs2);
        *(uint4*)(Ps + r * AH_STR + c8) = v;
    }
    __syncthreads();

    // hoist Q fragments (4 k16-steps x 4 regs)
    uint32_t qf[4][4];
    {
        const uint32_t* qp0 = (const uint32_t*)Ps + (wrow + lr) * 36 + lc;
#pragma unroll
        for (int kkb = 0; kkb < 4; ++kkb) {
            const uint32_t* qp = qp0 + kkb * 8;
            qf[kkb][0] = qp[0];
            qf[kkb][1] = qp[8 * 36];
            qf[kkb][2] = qp[4];
            qf[kkb][3] = qp[8 * 36 + 4];
        }
    }

    // per-lane ldmatrix address bases (shared-space)
    const uint32_t k0sm = smem_u32(K0);
    const uint32_t k1sm = smem_u32(K1);
    const uint32_t v0sm = smem_u32(V0);
    const uint32_t v1sm = smem_u32(V1);
    const int l7  = lane & 7;
    const int seg = (lane >> 3) & 1;
    const uint32_t kofs = (uint32_t)((l7 * 36 + seg * 4) * 4);       // K: row l7, col-seg
    const uint32_t vofs = (uint32_t)(((l7 + seg * 8) * 36) * 4);     // V: row l7+8seg

    float m0 = -1e30f, m1 = -1e30f, l0 = 0.f, l1 = 0.f;
    float oacc[8][4];
#pragma unroll
    for (int ni = 0; ni < 8; ++ni)
#pragma unroll
        for (int r = 0; r < 4; ++r) oacc[ni][r] = 0.f;

    const int gr0 = q0 + wrow + lr;
    const int gr1 = gr0 + 8;
    const int nkt = 2 * qb + 2;

    for (int kt = 0; kt < nkt; ++kt) {
        const int cur = kt & 1;
        cpa_wait0();
        __syncthreads();        // publish tile kt; buf !cur readers done

        if (kt + 1 < nkt) {
            __half* Kn = (cur ? K0 : K1);
            __half* Vn = (cur ? V0 : V1);
            const int kn0 = (kt + 1) << 6;
#pragma unroll
            for (int p = 0; p < 2; ++p) {
                const int row = fr + p * 32;
                cpa16(Kn + row * AH_STR + fseg,
                      bb + DM     + (size_t)(kn0 + row) * TD3 + fseg);
                cpa16(Vn + row * AH_STR + fseg,
                      bb + 2 * DM + (size_t)(kn0 + row) * TD3 + fseg);
            }
            cpa_commit();
        }

        const uint32_t ksm = (cur ? k1sm : k0sm) + kofs;
        const uint32_t vsm = (cur ? v1sm : v0sm) + vofs;

        // ---- S = Q @ K^T (16x64 per warp, fp16 k16) ----
        float sacc[8][4];
#pragma unroll
        for (int ni = 0; ni < 8; ++ni)
#pragma unroll
            for (int r = 0; r < 4; ++r) sacc[ni][r] = 0.f;

#pragma unroll
        for (int kkb = 0; kkb < 4; ++kkb) {
#pragma unroll
            for (int ni = 0; ni < 8; ++ni) {
                uint32_t b0, b1;
                ldsm2(b0, b1, ksm + (uint32_t)(ni * 1152 + kkb * 32));
                MMA_F16(sacc[ni], qf[kkb], b0, b1);
            }
        }

        // ---- causal mask ----
        if (kt >= 2 * qb) {
            const int k0t = kt << 6;
#pragma unroll
            for (int ni = 0; ni < 8; ++ni) {
                const int cb = k0t + ni * 8 + (lc << 1);
                if (cb     > gr0) sacc[ni][0] = -1e30f;
                if (cb + 1 > gr0) sacc[ni][1] = -1e30f;
                if (cb     > gr1) sacc[ni][2] = -1e30f;
                if (cb + 1 > gr1) sacc[ni][3] = -1e30f;
            }
        }

        // ---- online softmax in exp2 domain ----
        float rm0 = -1e30f, rm1 = -1e30f;
#pragma unroll
        for (int ni = 0; ni < 8; ++ni) {
            rm0 = fmaxf(rm0, fmaxf(sacc[ni][0], sacc[ni][1]));
            rm1 = fmaxf(rm1, fmaxf(sacc[ni][2], sacc[ni][3]));
        }
        rm0 = fmaxf(rm0, __shfl_xor_sync(0xffffffffu, rm0, 1, 4));
        rm0 = fmaxf(rm0, __shfl_xor_sync(0xffffffffu, rm0, 2, 4));
        rm1 = fmaxf(rm1, __shfl_xor_sync(0xffffffffu, rm1, 1, 4));
        rm1 = fmaxf(rm1, __shfl_xor_sync(0xffffffffu, rm1, 2, 4));

        const float mn0 = fmaxf(m0, rm0);
        const float mn1 = fmaxf(m1, rm1);
        const float c0f = ex2(m0 - mn0);
        const float c1f = ex2(m1 - mn1);
        m0 = mn0; m1 = mn1;

        float rs0 = 0.f, rs1 = 0.f;
#pragma unroll
        for (int ni = 0; ni < 8; ++ni) {
            sacc[ni][0] = ex2(sacc[ni][0] - mn0);
            sacc[ni][1] = ex2(sacc[ni][1] - mn0);
            sacc[ni][2] = ex2(sacc[ni][2] - mn1);
            sacc[ni][3] = ex2(sacc[ni][3] - mn1);
            rs0 += sacc[ni][0] + sacc[ni][1];
            rs1 += sacc[ni][2] + sacc[ni][3];
        }
        l0 = l0 * c0f + rs0;            // per-lane partial (quad-uniform c0f)
        l1 = l1 * c1f + rs1;
#pragma unroll
        for (int ni = 0; ni < 8; ++ni) {
            oacc[ni][0] *= c0f; oacc[ni][1] *= c0f;
            oacc[ni][2] *= c1f; oacc[ni][3] *= c1f;
        }

        // ---- stage P as fp16 (C-frag pairs -> half2, warp-private rows) ----
        {
            uint32_t* pr = (uint32_t*)Ps + (wrow + lr) * 36 + lc;
#pragma unroll
            for (int ni = 0; ni < 8; ++ni) {
                const __half2 a = __floats2half2_rn(sacc[ni][0], sacc[ni][1]);
                const __half2 c = __floats2half2_rn(sacc[ni][2], sacc[ni][3]);
                pr[ni * 4]          = *(const uint32_t*)&a;
                pr[8 * 36 + ni * 4] = *(const uint32_t*)&c;
            }
        }
        __syncwarp();

        // ---- O += P @ V (V via ldmatrix.trans) ----
#pragma unroll
        for (int kkb = 0; kkb < 4; ++kkb) {
            uint32_t pf[4];
            const uint32_t* pp =
                (const uint32_t*)Ps + (wrow + lr) * 36 + kkb * 8 + lc;
            pf[0] = pp[0];
            pf[1] = pp[8 * 36];
            pf[2] = pp[4];
            pf[3] = pp[8 * 36 + 4];
#pragma unroll
            for (int ni = 0; ni < 8; ++ni) {
                uint32_t b0, b1;
                ldsm2t(b0, b1, vsm + (uint32_t)(kkb * 2304 + ni * 16));
                MMA_F16(oacc[ni], pf, b0, b1);
            }
        }
        __syncwarp();   // P reads done before next iter's stores
    }

    // ---- epilogue: deferred l reduction; write fp16 (feeds GEMM2) ----
    l0 += __shfl_xor_sync(0xffffffffu, l0, 1, 4);
    l0 += __shfl_xor_sync(0xffffffffu, l0, 2, 4);
    l1 += __shfl_xor_sync(0xffffffffu, l1, 1, 4);
    l1 += __shfl_xor_sync(0xffffffffu, l1, 2, 4);
    const float inv0 = 1.f / l0;
    const float inv1 = 1.f / l1;
    __half* ob = out + (size_t)(b * T_ + gr0) * DM + h * DH + (lc << 1);
#pragma unroll
    for (int ni = 0; ni < 8; ++ni) {
        *(__half2*)(ob + ni * 8) =
            __floats2half2_rn(oacc[ni][0] * inv0, oacc[ni][1] * inv0);
        *(__half2*)(ob + (size_t)8 * DM + ni * 8) =
            __floats2half2_rn(oacc[ni][2] * inv1, oacc[ni][3] * inv1);
    }
}

// ---------------------------------------------------------------------------
extern "C" void kernel_launch(void* const* d_in, const int* in_sizes, int n_in,
                              void* d_out, int out_size)
{
    const float* x     = (const float*)d_in[0];
    const float* w_qkv = (const float*)d_in[1];
    const float* w_out = (const float*)d_in[2];
    float* out = (float*)d_out;

    __half *qkv16, *x16, *wq16, *wo16;
    cudaGetSymbolAddress((void**)&qkv16, g_qkv16);
    cudaGetSymbolAddress((void**)&x16,   g_x16);
    cudaGetSymbolAddress((void**)&wq16,  g_wq16);
    cudaGetSymbolAddress((void**)&wo16,  g_wo16);

    cudaFuncSetAttribute(hgemm<1>,
                         cudaFuncAttributeMaxDynamicSharedMemorySize, HGEMM_SMEM);
    cudaFuncSetAttribute(hgemm<0>,
                         cudaFuncAttributeMaxDynamicSharedMemorySize, HGEMM_SMEM);
    cudaFuncSetAttribute(attn_h,
                         cudaFuncAttributeMaxDynamicSharedMemorySize, ATTN_SMEM);

    // 0) prepasses: x -> fp16; weights -> fp16 transposed [N][K]
    cvt_h<<<(NTOK * DM) / 1024, 256>>>((const float4*)x, (uint2*)x16);
    cvt_ht<<<dim3((3 * DM) / 32, DM / 32), 256>>>(w_qkv, wq16, DM, 3 * DM);
    cvt_ht<<<dim3(DM / 32, DM / 32), 256>>>(w_out, wo16, DM, DM);

    // 1) qkv = x @ w_qkv  (fp16 MMA; fp16 output)
    hgemm<1><<<dim3((3 * DM) / 128, NTOK / 128), 256, HGEMM_SMEM>>>(
        x16, wq16, qkv16, NTOK, 3 * DM, DM);
    // 2) causal flash attention (full fp16 MMA; writes fp16 into x16)
    attn_h<<<dim3(T_ / 128, H_, B_), 256, ATTN_SMEM>>>(qkv16, x16);
    // 3) out = attn @ w_out  (fp16 MMA; final fp32 output)
    hgemm<0><<<dim3(DM / 128, NTOK / 128), 256, HGEMM_SMEM>>>(
        x16, wo16, out, NTOK, DM, DM);
}